// round 5
// baseline (speedup 1.0000x reference)
#include <cuda_runtime.h>
#include <cuda_fp16.h>

#define NU   200000
#define NI   100000
#define NN   300000
#define DIM  64
#define MAXE 2000000
#define E2   (2*MAXE)
#define NBRCAP (E2 + 3*NN + 64)   // CSR segments padded to 4-alignment

// ---------------- static device scratch ----------------
__device__ __align__(16) int     g_deg[NN];
__device__ __align__(16) int     g_start[NN];
__device__ __align__(16) int     g_cursor[NN];
__device__                int    g_total;
__device__ __align__(16) float   g_invdeg[NN];
__device__ __align__(16) float   g_en[NN];
__device__ __align__(16) __half2 g_egoh[(size_t)NN * 32];
__device__ __align__(16) int     g_nbr[NBRCAP];
__device__ __align__(16) __half2 g_xs0[(size_t)NN * 32];
__device__ __align__(16) __half2 g_xs1[(size_t)NN * 32];

// ---------------- helpers ----------------
__device__ __forceinline__ unsigned hadd2u(unsigned a, unsigned b) {
    __half2 ha = *reinterpret_cast<__half2*>(&a);
    __half2 hb = *reinterpret_cast<__half2*>(&b);
    __half2 r  = __hadd2(ha, hb);
    return *reinterpret_cast<unsigned*>(&r);
}
__device__ __forceinline__ float2 h2f(unsigned a) {
    return __half22float2(*reinterpret_cast<__half2*>(&a));
}

// ---------------- setup kernels ----------------

__global__ void k_count(const int* __restrict__ rows, const int* __restrict__ cols, int E) {
    int i = blockIdx.x * blockDim.x + threadIdx.x;
    if (i < E) {
        atomicAdd(&g_deg[rows[i]], 1);
        atomicAdd(&g_deg[cols[i] + NU], 1);
    }
}

// Block of 256 nodes: block-scan of 4-padded degrees (one atomic per block
// reserves the range -> every CSR segment starts 16B-aligned), invdeg, |ego|
// fp32-exact, ego->fp16, xs0 = invdeg*ego (fp16).
__global__ void k_assign(const float* __restrict__ ue, const float* __restrict__ ie) {
    __shared__ float sh_iv[256];
    __shared__ int   sh_ws[8];
    __shared__ int   sh_base;

    int tid  = threadIdx.x;
    int lane = tid & 31, wid = tid >> 5;
    int base = blockIdx.x * 256;
    int node = base + tid;

    int d = (node < NN) ? g_deg[node] : 0;
    int p = (d + 3) & ~3;                    // padded segment length

    int x = p;
    #pragma unroll
    for (int o = 1; o < 32; o <<= 1) {
        int t = __shfl_up_sync(0xffffffffu, x, o);
        if (lane >= o) x += t;
    }
    if (lane == 31) sh_ws[wid] = x;
    __syncthreads();
    if (wid == 0) {
        int s = (lane < 8) ? sh_ws[lane] : 0;
        #pragma unroll
        for (int o = 1; o < 8; o <<= 1) {
            int t = __shfl_up_sync(0xffffffffu, s, o);
            if (lane >= o) s += t;
        }
        if (lane < 8) sh_ws[lane] = s;
    }
    __syncthreads();
    if (tid == 0) sh_base = atomicAdd(&g_total, sh_ws[7]);
    __syncthreads();

    int excl = (wid ? sh_ws[wid - 1] : 0) + x - p;
    float iv = rsqrtf((float)d + 1e-7f);
    if (node < NN) {
        int st = sh_base + excl;
        g_start[node]  = st;
        g_cursor[node] = st;
        g_invdeg[node] = iv;
    }
    sh_iv[tid] = iv;
    __syncthreads();

    #pragma unroll 1
    for (int i = 0; i < 32; i++) {
        int ln = wid * 32 + i;
        int n  = base + ln;
        if (n >= NN) break;
        const float* ego = (n < NU) ? (ue + (size_t)n * DIM) : (ie + (size_t)(n - NU) * DIM);
        float2 e = *reinterpret_cast<const float2*>(ego + lane * 2);
        float en = e.x * e.x + e.y * e.y;
        #pragma unroll
        for (int o = 16; o; o >>= 1) en += __shfl_xor_sync(0xffffffffu, en, o);
        if (lane == 0) g_en[n] = fmaxf(sqrtf(en), 1e-8f);
        float ivn = sh_iv[ln];
        size_t q = (size_t)n * 32 + lane;
        g_egoh[q] = __floats2half2_rn(e.x, e.y);
        g_xs0[q]  = __floats2half2_rn(ivn * e.x, ivn * e.y);
    }
}

__global__ void k_fill(const int* __restrict__ rows, const int* __restrict__ cols, int E) {
    int i = blockIdx.x * blockDim.x + threadIdx.x;
    if (i < E) {
        int u = rows[i];
        int v = cols[i] + NU;
        int p = atomicAdd(&g_cursor[u], 1);
        g_nbr[p] = v;
        int q = atomicAdd(&g_cursor[v], 1);
        g_nbr[q] = u;
    }
}

// ---------------- fused layer: 2 nodes/warp, 16 lanes x 8B, unroll 8 ----------------
// MLP-oriented: 8 gathers in flight per lane, int4 index loads prefetched one
// iteration ahead, epilogue operands hoisted above the loop, level-2 HADD2 tree.
template <bool FIRST, bool LAST, bool FLIP>
__global__ void k_layer(float* __restrict__ acc) {
    const uint2* __restrict__ xin  = reinterpret_cast<const uint2*>(FLIP ? g_xs1 : g_xs0);
    uint2*       __restrict__ xout = reinterpret_cast<uint2*>(FLIP ? g_xs0 : g_xs1);

    int w    = blockIdx.x * (blockDim.x >> 5) + (threadIdx.x >> 5);
    int half = (threadIdx.x >> 4) & 1;
    int node = w * 2 + half;                 // exact grid
    int lane = threadIdx.x & 15;

    int start = g_start[node];
    int deg   = g_deg[node];
    int end   = start + deg;

    // hoisted epilogue operands (latency overlaps the gather loop)
    float iv = g_invdeg[node];
    float en = g_en[node];
    uint2 ev = reinterpret_cast<const uint2*>(g_egoh)[(size_t)node * 16 + lane];

    float h0 = 0.f, h1 = 0.f, h2 = 0.f, h3 = 0.f;
    int j = start;

    int4 ia, ib;
    if (j + 8 <= end) {
        ia = *reinterpret_cast<const int4*>(g_nbr + j);
        ib = *reinterpret_cast<const int4*>(g_nbr + j + 4);
    }
    while (j + 8 <= end) {
        int s0 = ia.x, s1 = ia.y, s2 = ia.z, s3 = ia.w;
        int s4 = ib.x, s5 = ib.y, s6 = ib.z, s7 = ib.w;
        uint2 v0 = xin[(size_t)s0 * 16 + lane];
        uint2 v1 = xin[(size_t)s1 * 16 + lane];
        uint2 v2 = xin[(size_t)s2 * 16 + lane];
        uint2 v3 = xin[(size_t)s3 * 16 + lane];
        uint2 v4 = xin[(size_t)s4 * 16 + lane];
        uint2 v5 = xin[(size_t)s5 * 16 + lane];
        uint2 v6 = xin[(size_t)s6 * 16 + lane];
        uint2 v7 = xin[(size_t)s7 * 16 + lane];
        j += 8;
        if (j + 8 <= end) {                   // prefetch next iteration's indices
            ia = *reinterpret_cast<const int4*>(g_nbr + j);
            ib = *reinterpret_cast<const int4*>(g_nbr + j + 4);
        }
        // level-1 pairs
        unsigned a01x = hadd2u(v0.x, v1.x), a01y = hadd2u(v0.y, v1.y);
        unsigned a23x = hadd2u(v2.x, v3.x), a23y = hadd2u(v2.y, v3.y);
        unsigned a45x = hadd2u(v4.x, v5.x), a45y = hadd2u(v4.y, v5.y);
        unsigned a67x = hadd2u(v6.x, v7.x), a67y = hadd2u(v6.y, v7.y);
        // level-2
        unsigned bax = hadd2u(a01x, a23x), bay = hadd2u(a01y, a23y);
        unsigned bbx = hadd2u(a45x, a67x), bby = hadd2u(a45y, a67y);
        float2 f;
        f = h2f(bax); h0 += f.x; h1 += f.y;
        f = h2f(bay); h2 += f.x; h3 += f.y;
        f = h2f(bbx); h0 += f.x; h1 += f.y;
        f = h2f(bby); h2 += f.x; h3 += f.y;
    }
    if (j + 4 <= end) {
        int4 ic = *reinterpret_cast<const int4*>(g_nbr + j);
        uint2 v0 = xin[(size_t)ic.x * 16 + lane];
        uint2 v1 = xin[(size_t)ic.y * 16 + lane];
        uint2 v2 = xin[(size_t)ic.z * 16 + lane];
        uint2 v3 = xin[(size_t)ic.w * 16 + lane];
        j += 4;
        unsigned a01x = hadd2u(v0.x, v1.x), a01y = hadd2u(v0.y, v1.y);
        unsigned a23x = hadd2u(v2.x, v3.x), a23y = hadd2u(v2.y, v3.y);
        unsigned bx = hadd2u(a01x, a23x), by = hadd2u(a01y, a23y);
        float2 f;
        f = h2f(bx); h0 += f.x; h1 += f.y;
        f = h2f(by); h2 += f.x; h3 += f.y;
    }
    for (; j < end; ++j) {
        uint2 v = xin[(size_t)g_nbr[j] * 16 + lane];
        float2 f;
        f = h2f(v.x); h0 += f.x; h1 += f.y;
        f = h2f(v.y); h2 += f.x; h3 += f.y;
    }

    h0 *= iv; h1 *= iv; h2 *= iv; h3 *= iv;

    float2 e0 = h2f(ev.x);
    float2 e1 = h2f(ev.y);

    float dot = h0 * e0.x + h1 * e0.y + h2 * e1.x + h3 * e1.y;
    float hn  = h0 * h0 + h1 * h1 + h2 * h2 + h3 * h3;
    #pragma unroll
    for (int o = 8; o; o >>= 1) {
        dot += __shfl_xor_sync(0xffffffffu, dot, o);
        hn  += __shfl_xor_sync(0xffffffffu, hn,  o);
    }

    float wgt = dot / (fmaxf(sqrtf(hn), 1e-8f) * en);
    float o0 = wgt * h0, o1 = wgt * h1, o2 = wgt * h2, o3 = wgt * h3;

    float4* ap = reinterpret_cast<float4*>(acc + (size_t)node * DIM + lane * 4);
    if (FIRST) {
        float4 o; o.x = o0; o.y = o1; o.z = o2; o.w = o3;
        *ap = o;
    } else {
        float4 a4 = *ap;
        a4.x += o0; a4.y += o1; a4.z += o2; a4.w += o3;
        *ap = a4;
    }
    if (!LAST) {
        uint2 xo;
        __half2 p0 = __floats2half2_rn(iv * o0, iv * o1);
        __half2 p1 = __floats2half2_rn(iv * o2, iv * o3);
        xo.x = *reinterpret_cast<unsigned*>(&p0);
        xo.y = *reinterpret_cast<unsigned*>(&p1);
        xout[(size_t)node * 16 + lane] = xo;
    }
}

// ---------------- launch ----------------

extern "C" void kernel_launch(void* const* d_in, const int* in_sizes, int n_in,
                              void* d_out, int out_size) {
    const float* ue   = (const float*)d_in[0];
    const float* ie   = (const float*)d_in[1];
    const int*   rows = (const int*)d_in[2];
    const int*   cols = (const int*)d_in[3];
    int E = in_sizes[2];
    if (E > MAXE) E = MAXE;
    float* acc = (float*)d_out;

    void* p_deg = nullptr;
    void* p_tot = nullptr;
    cudaGetSymbolAddress(&p_deg, g_deg);
    cudaGetSymbolAddress(&p_tot, g_total);
    cudaMemsetAsync(p_deg, 0, sizeof(int) * NN);
    cudaMemsetAsync(p_tot, 0, sizeof(int));

    const int T = 256;
    k_count <<<(E + T - 1) / T, T>>>(rows, cols, E);        // launch 0
    k_assign<<<(NN + 255) / 256, 256>>>(ue, ie);            // launch 1
    k_fill  <<<(E + T - 1) / T, T>>>(rows, cols, E);        // launch 2

    const int LBLK = NN / 2 / 8;   // 18750 blocks (exact)
    k_layer<true,  false, false><<<LBLK, T>>>(acc);         // launch 3 (ncu target)
    k_layer<false, false, true ><<<LBLK, T>>>(acc);         // launch 4
    k_layer<false, true,  false><<<LBLK, T>>>(acc);         // launch 5
}